// round 5
// baseline (speedup 1.0000x reference)
#include <cuda_runtime.h>

#define N_NODES 100000
#define N_EDGES 1600000
#define DF 128
#define HF 32
#define NL 4
#define CHUNK 512
#define NCH ((N_NODES + CHUNK - 1) / CHUNK)   // 196

typedef unsigned long long u64;

// ---------------- device scratch (no allocation allowed) ----------------
__device__ float g_P [N_NODES * HF];
__device__ float g_SP[N_NODES * HF];
__device__ float g_Y2[N_NODES * HF];
__device__ float g_X [N_NODES * DF];
__device__ int   g_deg   [N_NODES];
__device__ int   g_rowptr[N_NODES + 1];
__device__ int   g_cursor[N_NODES];
__device__ int   g_col   [N_EDGES];
__device__ int   g_bsum[NCH];
__device__ int   g_boff[NCH];
__device__ float g_sumA[HF], g_sqA[HF];
__device__ float g_sumB[HF], g_sqB[HF];
__device__ unsigned g_cntA, g_cntB;
__device__ float g_a [HF], g_c [HF];     // BN1 coefs (consumed by gemm2)
__device__ float g_a2[HF], g_c2[HF];     // BN2 coefs (consumed by gemm3)
__device__ int   g_idx64;

// ---------------- f32x2 helpers ----------------
__device__ __forceinline__ u64 pk2(float v) {
    u64 r; asm("mov.b64 %0,{%1,%1};" : "=l"(r) : "f"(v)); return r;
}
__device__ __forceinline__ void fma2(u64& d, u64 a, u64 b) {
    asm("fma.rn.f32x2 %0,%1,%2,%3;" : "=l"(d) : "l"(a), "l"(b), "l"(d));
}
__device__ __forceinline__ float2 up2(u64 v) {
    float2 r; asm("mov.b64 {%0,%1},%2;" : "=f"(r.x), "=f"(r.y) : "l"(v)); return r;
}

// ---------------- index dtype detection (int64 vs int32) ----------------
__global__ void detect_kernel(const int* __restrict__ idx)
{
    int lane = threadIdx.x;
    int bad = 0;
    for (int i = lane; i < 2048; i += 32) bad |= (idx[2 * i + 1] != 0);
    unsigned m = __ballot_sync(0xffffffffu, bad);
    if (lane == 0) g_idx64 = (m == 0);
}

// ---------------- CSR build ----------------
__global__ __launch_bounds__(256) void deg_kernel(const int* __restrict__ idx)
{
    int e = blockIdx.x * blockDim.x + threadIdx.x;
    if (e >= N_EDGES) return;
    int d = g_idx64 ? idx[2 * (N_EDGES + e)] : idx[N_EDGES + e];
    atomicAdd(&g_deg[d], 1);
}

__global__ __launch_bounds__(256) void chunksum_kernel()
{
    __shared__ int ss[256];
    int c = blockIdx.x, t = threadIdx.x;
    int i0 = c * CHUNK + t;
    int v = 0;
    if (i0 < N_NODES) v += g_deg[i0];
    if (t + 256 < CHUNK && i0 + 256 < N_NODES) v += g_deg[i0 + 256];
    ss[t] = v; __syncthreads();
    for (int o = 128; o > 0; o >>= 1) {
        if (t < o) ss[t] += ss[t + o];
        __syncthreads();
    }
    if (t == 0) g_bsum[c] = ss[0];
}

__global__ void scanpart_kernel()
{
    if (threadIdx.x == 0) {
        int acc = 0;
        for (int i = 0; i < NCH; i++) { g_boff[i] = acc; acc += g_bsum[i]; }
    }
}

__global__ __launch_bounds__(CHUNK) void chunkscan_kernel()
{
    __shared__ int sd[CHUNK];
    int c = blockIdx.x, t = threadIdx.x;
    int i = c * CHUNK + t;
    int v = (i < N_NODES) ? g_deg[i] : 0;
    sd[t] = v; __syncthreads();
    for (int off = 1; off < CHUNK; off <<= 1) {
        int x = (t >= off) ? sd[t - off] : 0;
        __syncthreads();
        sd[t] += x;
        __syncthreads();
    }
    int excl = sd[t] - v;
    if (i < N_NODES) {
        int rp = g_boff[c] + excl;
        g_rowptr[i] = rp;
        g_cursor[i] = rp;
    }
    if (i == 0) g_rowptr[N_NODES] = N_EDGES;
}

__global__ __launch_bounds__(256) void fill_kernel(const int* __restrict__ idx)
{
    int e = blockIdx.x * blockDim.x + threadIdx.x;
    if (e >= N_EDGES) return;
    int s, d;
    if (g_idx64) { s = idx[2 * e]; d = idx[2 * (N_EDGES + e)]; }
    else         { s = idx[e];     d = idx[N_EDGES + e];       }
    int pos = atomicAdd(&g_cursor[d], 1);
    g_col[pos] = s;
}

// ---------------- GEMM1: P = X @ W1^T (f32x2, pre-duplicated W) ----------
__global__ __launch_bounds__(128) void gemm1_kernel(
    const float* __restrict__ X, const float* __restrict__ W,
    float* __restrict__ P)
{
    __shared__ __align__(16) float Xs[32 * 68];   // [k][node] 8704 B
    __shared__ __align__(16) u64   Wd[128 * 34];  // [k][col] dup, 34816 B

    const int tid = threadIdx.x;
    const int node0 = blockIdx.x * 64;
    const int cg = tid & 7;    // cols 4cg..4cg+3
    const int ng = tid >> 3;   // nodes 4ng..4ng+3 (two f32x2 pairs)

    for (int i = tid; i < 32 * 128; i += 128) {
        int c = i >> 7, k = i & 127;
        Wd[k * 34 + c] = pk2(W[i]);
    }

    u64 acc[2][4] = {};   // [node pair][col]

    for (int kk = 0; kk < 128; kk += 32) {
        __syncthreads();
        for (int i = tid; i < 64 * 8; i += 128) {
            int node = i >> 3, k4 = i & 7;
            int gnode = node0 + node;
            float4 v = make_float4(0.f, 0.f, 0.f, 0.f);
            if (gnode < N_NODES)
                v = ((const float4*)(X + (size_t)gnode * DF + kk))[k4];
            int kb = 4 * k4;
            Xs[(kb + 0) * 68 + node] = v.x;
            Xs[(kb + 1) * 68 + node] = v.y;
            Xs[(kb + 2) * 68 + node] = v.z;
            Xs[(kb + 3) * 68 + node] = v.w;
        }
        __syncthreads();

#pragma unroll
        for (int k = 0; k < 32; k++) {
            ulonglong2 ap = *(const ulonglong2*)&Xs[k * 68 + 4 * ng];
            const u64* wr = &Wd[(kk + k) * 34 + 4 * cg];
            ulonglong2 w01 = *(const ulonglong2*)wr;
            ulonglong2 w23 = *(const ulonglong2*)(wr + 2);
            fma2(acc[0][0], ap.x, w01.x); fma2(acc[0][1], ap.x, w01.y);
            fma2(acc[0][2], ap.x, w23.x); fma2(acc[0][3], ap.x, w23.y);
            fma2(acc[1][0], ap.y, w01.x); fma2(acc[1][1], ap.y, w01.y);
            fma2(acc[1][2], ap.y, w23.x); fma2(acc[1][3], ap.y, w23.y);
        }
    }

#pragma unroll
    for (int p = 0; p < 2; p++) {
        float2 c0 = up2(acc[p][0]), c1 = up2(acc[p][1]);
        float2 c2 = up2(acc[p][2]), c3 = up2(acc[p][3]);
        int n0 = node0 + 4 * ng + 2 * p;
        if (n0 < N_NODES)
            ((float4*)(P + (size_t)n0 * HF + 4 * cg))[0] =
                make_float4(c0.x, c1.x, c2.x, c3.x);
        if (n0 + 1 < N_NODES)
            ((float4*)(P + (size_t)(n0 + 1) * HF + 4 * cg))[0] =
                make_float4(c0.y, c1.y, c2.y, c3.y);
    }
}

// -------- gather: SP[d] = (1+eps)P[d] + b1 + sum_{s in N(d)} P[s] --------
// warp per dst node; fused BN1 stats + coef (last block).
__global__ __launch_bounds__(256) void gather_kernel(
    const float* __restrict__ P, const float* __restrict__ b,
    const float* __restrict__ eps_arr, int layer,
    const float* __restrict__ gamma, const float* __restrict__ beta,
    float* __restrict__ SP)
{
    __shared__ float bsum[32], bsq[32];
    __shared__ bool  is_last;
    const int lane = threadIdx.x & 31;
    const int wid  = threadIdx.x >> 5;
    if (threadIdx.x < 32) { bsum[threadIdx.x] = 0.f; bsq[threadIdx.x] = 0.f; }
    __syncthreads();

    const float ep = 1.0f + eps_arr[layer];
    const float bb = b[lane];
    float psum = 0.f, psq = 0.f;

    const int warpg = blockIdx.x * 8 + wid;
    const int nwarp = gridDim.x * 8;
    for (int d = warpg; d < N_NODES; d += nwarp) {
        float s = fmaf(ep, P[d * HF + lane], bb);
        const int beg = g_rowptr[d], end = g_rowptr[d + 1];
        for (int base = beg; base < end; base += 32) {
            const int cnt = min(32, end - base);
            int idxv = (base + lane < end) ? g_col[base + lane] : 0;
            int j = 0;
            for (; j + 4 <= cnt; j += 4) {
                int s0 = __shfl_sync(0xffffffffu, idxv, j);
                int s1 = __shfl_sync(0xffffffffu, idxv, j + 1);
                int s2 = __shfl_sync(0xffffffffu, idxv, j + 2);
                int s3 = __shfl_sync(0xffffffffu, idxv, j + 3);
                float v0 = P[s0 * HF + lane];
                float v1 = P[s1 * HF + lane];
                float v2 = P[s2 * HF + lane];
                float v3 = P[s3 * HF + lane];
                s += (v0 + v1) + (v2 + v3);
            }
            for (; j < cnt; j++) {
                int ss = __shfl_sync(0xffffffffu, idxv, j);
                s += P[ss * HF + lane];
            }
        }
        SP[d * HF + lane] = s;
        psum += s; psq += s * s;
    }

    atomicAdd(&bsum[lane], psum);
    atomicAdd(&bsq [lane], psq);
    __syncthreads();
    if (threadIdx.x < 32) {
        atomicAdd(&g_sumA[threadIdx.x], bsum[threadIdx.x]);
        atomicAdd(&g_sqA [threadIdx.x], bsq [threadIdx.x]);
    }
    __threadfence();
    __syncthreads();
    if (threadIdx.x == 0)
        is_last = (atomicAdd(&g_cntA, 1u) == (unsigned)gridDim.x - 1u);
    __syncthreads();
    if (is_last && threadIdx.x < 32) {
        int j = threadIdx.x;
        float m   = g_sumA[j] * (1.0f / N_NODES);
        float var = g_sqA[j] * (1.0f / N_NODES) - m * m;
        float a = gamma[j] * rsqrtf(var + 1e-5f);
        g_a[j] = a;
        g_c[j] = beta[j] - m * a;
        g_sumA[j] = 0.f; g_sqA[j] = 0.f;
        if (j == 0) g_cntA = 0u;
    }
}

// ---------------- GEMM2: Y2 = relu(a*Y1+c) @ W2^T + b2 (fused stats) -----
__global__ __launch_bounds__(128) void gemm2_kernel(
    const float* __restrict__ Y1, const float* __restrict__ W,
    const float* __restrict__ b, const float* __restrict__ gamma,
    const float* __restrict__ beta, float* __restrict__ Y2)
{
    __shared__ __align__(16) float Xs[32 * 68];
    __shared__ __align__(16) u64   Wd[32 * 34];
    __shared__ float rsum[16][33];
    __shared__ float rsq [16][33];
    __shared__ bool  is_last;

    const int tid = threadIdx.x;
    const int node0 = blockIdx.x * 64;
    const int cg = tid & 7;
    const int ng = tid >> 3;

    for (int i = tid; i < 32 * 32; i += 128) {
        int c = i >> 5, k = i & 31;
        Wd[k * 34 + c] = pk2(W[i]);
    }
    for (int i = tid; i < 64 * 8; i += 128) {
        int node = i >> 3, k4 = i & 7;
        int gnode = node0 + node;
        float4 v = make_float4(0.f, 0.f, 0.f, 0.f);
        if (gnode < N_NODES)
            v = ((const float4*)(Y1 + (size_t)gnode * HF))[k4];
        int kb = 4 * k4;
        v.x = fmaxf(fmaf(g_a[kb + 0], v.x, g_c[kb + 0]), 0.f);
        v.y = fmaxf(fmaf(g_a[kb + 1], v.y, g_c[kb + 1]), 0.f);
        v.z = fmaxf(fmaf(g_a[kb + 2], v.z, g_c[kb + 2]), 0.f);
        v.w = fmaxf(fmaf(g_a[kb + 3], v.w, g_c[kb + 3]), 0.f);
        Xs[(kb + 0) * 68 + node] = v.x;
        Xs[(kb + 1) * 68 + node] = v.y;
        Xs[(kb + 2) * 68 + node] = v.z;
        Xs[(kb + 3) * 68 + node] = v.w;
    }
    __syncthreads();

    u64 acc[2][4] = {};
#pragma unroll
    for (int k = 0; k < 32; k++) {
        ulonglong2 ap = *(const ulonglong2*)&Xs[k * 68 + 4 * ng];
        const u64* wr = &Wd[k * 34 + 4 * cg];
        ulonglong2 w01 = *(const ulonglong2*)wr;
        ulonglong2 w23 = *(const ulonglong2*)(wr + 2);
        fma2(acc[0][0], ap.x, w01.x); fma2(acc[0][1], ap.x, w01.y);
        fma2(acc[0][2], ap.x, w23.x); fma2(acc[0][3], ap.x, w23.y);
        fma2(acc[1][0], ap.y, w01.x); fma2(acc[1][1], ap.y, w01.y);
        fma2(acc[1][2], ap.y, w23.x); fma2(acc[1][3], ap.y, w23.y);
    }

    const float b0 = b[4 * cg + 0], b1v = b[4 * cg + 1];
    const float b2v = b[4 * cg + 2], b3v = b[4 * cg + 3];
    float cs[4] = {0.f, 0.f, 0.f, 0.f};
    float cq[4] = {0.f, 0.f, 0.f, 0.f};
#pragma unroll
    for (int p = 0; p < 2; p++) {
        float2 c0 = up2(acc[p][0]), c1 = up2(acc[p][1]);
        float2 c2 = up2(acc[p][2]), c3 = up2(acc[p][3]);
        float4 oA = make_float4(c0.x + b0, c1.x + b1v, c2.x + b2v, c3.x + b3v);
        float4 oB = make_float4(c0.y + b0, c1.y + b1v, c2.y + b2v, c3.y + b3v);
        int n0 = node0 + 4 * ng + 2 * p;
        if (n0 < N_NODES) {
            ((float4*)(Y2 + (size_t)n0 * HF + 4 * cg))[0] = oA;
            cs[0] += oA.x; cs[1] += oA.y; cs[2] += oA.z; cs[3] += oA.w;
            cq[0] += oA.x * oA.x; cq[1] += oA.y * oA.y;
            cq[2] += oA.z * oA.z; cq[3] += oA.w * oA.w;
        }
        if (n0 + 1 < N_NODES) {
            ((float4*)(Y2 + (size_t)(n0 + 1) * HF + 4 * cg))[0] = oB;
            cs[0] += oB.x; cs[1] += oB.y; cs[2] += oB.z; cs[3] += oB.w;
            cq[0] += oB.x * oB.x; cq[1] += oB.y * oB.y;
            cq[2] += oB.z * oB.z; cq[3] += oB.w * oB.w;
        }
    }
#pragma unroll
    for (int j = 0; j < 4; j++) { rsum[ng][4 * cg + j] = cs[j]; rsq[ng][4 * cg + j] = cq[j]; }
    __syncthreads();
    if (tid < 32) {
        float ts = 0.f, tq = 0.f;
#pragma unroll
        for (int r = 0; r < 16; r++) { ts += rsum[r][tid]; tq += rsq[r][tid]; }
        atomicAdd(&g_sumB[tid], ts);
        atomicAdd(&g_sqB [tid], tq);
    }
    __threadfence();
    __syncthreads();
    if (tid == 0)
        is_last = (atomicAdd(&g_cntB, 1u) == (unsigned)gridDim.x - 1u);
    __syncthreads();
    if (is_last && tid < 32) {
        int j = tid;
        float m   = g_sumB[j] * (1.0f / N_NODES);
        float var = g_sqB[j] * (1.0f / N_NODES) - m * m;
        float a = gamma[j] * rsqrtf(var + 1e-5f);
        g_a2[j] = a;
        g_c2[j] = beta[j] - m * a;
        g_sumB[j] = 0.f; g_sqB[j] = 0.f;
        if (j == 0) g_cntB = 0u;
    }
}

// ---------------- GEMM3: Xout = relu(a2*Y2+c2) @ W3^T + b3 ----------------
__global__ __launch_bounds__(256) void gemm3_kernel(
    const float* __restrict__ Y2, const float* __restrict__ W,
    const float* __restrict__ b, float* __restrict__ Xout)
{
    __shared__ __align__(16) float Xs[32 * 68];    // 8704 B
    __shared__ __align__(16) u64   Wd[32 * 132];   // [h][d] dup, 33792 B

    const int tid = threadIdx.x;
    const int node0 = blockIdx.x * 64;
    const int cg = tid & 31;        // cols 4cg..4cg+3 (of 128)
    const int ng = tid >> 5;        // nodes 8ng..8ng+7 (4 pairs)

    for (int i = tid; i < 128 * 32; i += 256) {
        int d = i >> 5, h = i & 31;
        Wd[h * 132 + d] = pk2(W[i]);
    }
    for (int i = tid; i < 64 * 8; i += 256) {
        int node = i >> 3, k4 = i & 7;
        int gnode = node0 + node;
        float4 v = make_float4(0.f, 0.f, 0.f, 0.f);
        if (gnode < N_NODES)
            v = ((const float4*)(Y2 + (size_t)gnode * HF))[k4];
        int kb = 4 * k4;
        v.x = fmaxf(fmaf(g_a2[kb + 0], v.x, g_c2[kb + 0]), 0.f);
        v.y = fmaxf(fmaf(g_a2[kb + 1], v.y, g_c2[kb + 1]), 0.f);
        v.z = fmaxf(fmaf(g_a2[kb + 2], v.z, g_c2[kb + 2]), 0.f);
        v.w = fmaxf(fmaf(g_a2[kb + 3], v.w, g_c2[kb + 3]), 0.f);
        Xs[(kb + 0) * 68 + node] = v.x;
        Xs[(kb + 1) * 68 + node] = v.y;
        Xs[(kb + 2) * 68 + node] = v.z;
        Xs[(kb + 3) * 68 + node] = v.w;
    }
    __syncthreads();

    u64 acc[4][4] = {};   // [node pair][col]
#pragma unroll
    for (int k = 0; k < 32; k++) {
        ulonglong2 apA = *(const ulonglong2*)&Xs[k * 68 + 8 * ng];
        ulonglong2 apB = *(const ulonglong2*)&Xs[k * 68 + 8 * ng + 4];
        const u64* wr = &Wd[k * 132 + 4 * cg];
        ulonglong2 w01 = *(const ulonglong2*)wr;
        ulonglong2 w23 = *(const ulonglong2*)(wr + 2);
        fma2(acc[0][0], apA.x, w01.x); fma2(acc[0][1], apA.x, w01.y);
        fma2(acc[0][2], apA.x, w23.x); fma2(acc[0][3], apA.x, w23.y);
        fma2(acc[1][0], apA.y, w01.x); fma2(acc[1][1], apA.y, w01.y);
        fma2(acc[1][2], apA.y, w23.x); fma2(acc[1][3], apA.y, w23.y);
        fma2(acc[2][0], apB.x, w01.x); fma2(acc[2][1], apB.x, w01.y);
        fma2(acc[2][2], apB.x, w23.x); fma2(acc[2][3], apB.x, w23.y);
        fma2(acc[3][0], apB.y, w01.x); fma2(acc[3][1], apB.y, w01.y);
        fma2(acc[3][2], apB.y, w23.x); fma2(acc[3][3], apB.y, w23.y);
    }

    const float b0 = b[4 * cg + 0], b1v = b[4 * cg + 1];
    const float b2v = b[4 * cg + 2], b3v = b[4 * cg + 3];
#pragma unroll
    for (int p = 0; p < 4; p++) {
        float2 c0 = up2(acc[p][0]), c1 = up2(acc[p][1]);
        float2 c2 = up2(acc[p][2]), c3 = up2(acc[p][3]);
        int n0 = node0 + 8 * ng + 2 * p;
        if (n0 < N_NODES)
            ((float4*)(Xout + (size_t)n0 * DF + 4 * cg))[0] =
                make_float4(c0.x + b0, c1.x + b1v, c2.x + b2v, c3.x + b3v);
        if (n0 + 1 < N_NODES)
            ((float4*)(Xout + (size_t)(n0 + 1) * DF + 4 * cg))[0] =
                make_float4(c0.y + b0, c1.y + b1v, c2.y + b2v, c3.y + b3v);
    }
}

// --------------------------------- launch ---------------------------------
extern "C" void kernel_launch(void* const* d_in, const int* in_sizes, int n_in,
                              void* d_out, int out_size)
{
    (void)in_sizes; (void)n_in; (void)out_size;
    const float* X0  = (const float*)d_in[0];
    const int*   idx = (const int*)  d_in[1];
    const float* eps = (const float*)d_in[2];
    const float* W1  = (const float*)d_in[3];
    const float* b1  = (const float*)d_in[4];
    const float* g1  = (const float*)d_in[5];
    const float* bt1 = (const float*)d_in[6];
    const float* W2  = (const float*)d_in[7];
    const float* b2  = (const float*)d_in[8];
    const float* g2  = (const float*)d_in[9];
    const float* bt2 = (const float*)d_in[10];
    const float* W3  = (const float*)d_in[11];
    const float* b3  = (const float*)d_in[12];
    float* out = (float*)d_out;

    float *pP, *pSP, *pY2, *pX;
    void* pDeg;
    cudaGetSymbolAddress((void**)&pP,  g_P);
    cudaGetSymbolAddress((void**)&pSP, g_SP);
    cudaGetSymbolAddress((void**)&pY2, g_Y2);
    cudaGetSymbolAddress((void**)&pX,  g_X);
    cudaGetSymbolAddress(&pDeg, g_deg);

    const int gemm_blocks = (N_NODES + 63) / 64;       // 1563
    const int edge_blocks = (N_EDGES + 255) / 256;     // 6250

    // --- CSR build (once per call; edge list identical across layers) ---
    detect_kernel<<<1, 32>>>(idx);
    cudaMemsetAsync(pDeg, 0, N_NODES * sizeof(int), 0);
    deg_kernel<<<edge_blocks, 256>>>(idx);
    chunksum_kernel<<<NCH, 256>>>();
    scanpart_kernel<<<1, 32>>>();
    chunkscan_kernel<<<NCH, CHUNK>>>();
    fill_kernel<<<edge_blocks, 256>>>(idx);

    for (int l = 0; l < NL; l++) {
        const float* Xc = (l == 0) ? X0 : pX;
        float* Xn = (l == NL - 1) ? out : pX;

        gemm1_kernel<<<gemm_blocks, 128>>>(Xc, W1 + l * HF * DF, pP);
        gather_kernel<<<592, 256>>>(pP, b1 + l * HF, eps, l,
                                    g1 + l * HF, bt1 + l * HF, pSP);
        gemm2_kernel<<<gemm_blocks, 128>>>(pSP, W2 + l * HF * HF, b2 + l * HF,
                                           g2 + l * HF, bt2 + l * HF, pY2);
        gemm3_kernel<<<gemm_blocks, 256>>>(pY2, W3 + l * DF * HF, b3 + l * DF, Xn);
    }
}